// round 1
// baseline (speedup 1.0000x reference)
#include <cuda_runtime.h>
#include <cuda_fp16.h>
#include <mma.h>

using namespace nvcuda;

#define DD 1024
#define HH 4096
#define NB 8
#define LL 768
#define MT 6144   // NB*LL
#define NE 4

#define BM 128
#define BN 128
#define BK 32
#define LDA 48    // BK + 16 halfs pad (32B-aligned rows)
#define LDB 144   // BN + 16 halfs pad

// ---------------- scratch (device globals; no allocation) ----------------
__device__ __half g_Xh[(size_t)MT * DD];
__device__ __half g_W1e[(size_t)NE * DD * HH];
__device__ __half g_W2e[(size_t)NE * HH * DD];
__device__ __half g_W1s[(size_t)DD * HH];
__device__ __half g_W2s[(size_t)HH * DD];
__device__ __half g_H[(size_t)MT * HH];
__device__ float  g_partial[NB * 6 * DD];
__device__ float  g_wbe[NB * NE];

// ---------------- helpers ----------------
__device__ __forceinline__ void cp_async16(void* smem, const void* gmem) {
    unsigned s = (unsigned)__cvta_generic_to_shared(smem);
    asm volatile("cp.async.cg.shared.global [%0], [%1], 16;\n" :: "r"(s), "l"(gmem) : "memory");
}
__device__ __forceinline__ void cp_commit() { asm volatile("cp.async.commit_group;\n" ::: "memory"); }
__device__ __forceinline__ void cp_wait0()  { asm volatile("cp.async.wait_group 0;\n" ::: "memory"); }

__device__ __forceinline__ float gelu_t(float v) {
    float c = v + 0.044715f * v * v * v;
    return 0.5f * v * (1.f + tanhf(0.7978845608028654f * c));
}

// per-M-tile weight: batch gating weight x third-mask; exact 0 => skip tile
__device__ __forceinline__ float tile_weight(int expert, int bm) {
    if (expert < 0) return 1.f;
    int b = bm / 6;             // 6 tiles of 128 tokens per batch
    int third = (bm % 6) >> 1;  // 0 head, 1 wrist, 2 proprio
    if (expert == 1 && third == 1) return 0.f;
    if (expert == 2 && third == 0) return 0.f;
    return g_wbe[b * NE + expert];
}

__device__ __forceinline__ void load_tiles(__half* As, __half* Bs,
        const __half* __restrict__ A, const __half* __restrict__ B,
        int m0, int n0, int k0, int K, int N, int tid)
{
    // A tile: 128 rows x 32 halfs = 512 x 16B chunks
    #pragma unroll
    for (int i = 0; i < 2; i++) {
        int idx = tid + i * 256;
        int r = idx >> 2;
        int c = (idx & 3) << 3;
        cp_async16(As + r * LDA + c, A + (size_t)(m0 + r) * K + k0 + c);
    }
    // B tile: 32 rows x 128 halfs = 512 x 16B chunks
    #pragma unroll
    for (int i = 0; i < 2; i++) {
        int idx = tid + i * 256;
        int r = idx >> 4;
        int c = (idx & 15) << 3;
        cp_async16(Bs + r * LDB + c, B + (size_t)(k0 + r) * N + n0 + c);
    }
}

// ---------------- gating stage A: partial token sums per (batch, 128-token chunk) ----------------
__global__ void k_stageA(const float* __restrict__ x) {
    int b = blockIdx.x, c = blockIdx.y, t = threadIdx.x;
    const float* base = x + ((size_t)(b * LL + c * 128)) * DD;
    for (int d = t; d < DD; d += 256) {
        float s = 0.f;
        #pragma unroll 4
        for (int l = 0; l < 128; ++l) s += base[(size_t)l * DD + d];
        g_partial[(b * 6 + c) * DD + d] = s;
    }
}

// ---------------- gating stage B: logits, modulation, softmax, top-2, renorm ----------------
__global__ void k_gate(const float* __restrict__ gate_w, const float* __restrict__ gate_b,
                       const float* __restrict__ time_cond, const float* __restrict__ time_w,
                       const float* __restrict__ time_b)
{
    int b = blockIdx.x, t = threadIdx.x;
    __shared__ float red[12][256];
    float acc[12];
    #pragma unroll
    for (int k = 0; k < 12; k++) acc[k] = 0.f;
    for (int d = t; d < DD; d += 256) {
        float h = g_partial[(b*6+0)*DD+d] + g_partial[(b*6+1)*DD+d];
        float w = g_partial[(b*6+2)*DD+d] + g_partial[(b*6+3)*DD+d];
        float p = g_partial[(b*6+4)*DD+d] + g_partial[(b*6+5)*DD+d];
        float full = (h + w + p) * (1.f / 768.f);
        float hp   = (h + p) * (1.f / 512.f);
        float wp   = (w + p) * (1.f / 512.f);
        #pragma unroll
        for (int e = 0; e < 4; e++)
            acc[e] += full * gate_w[d*4+e] + hp * gate_w[(DD+d)*4+e] + wp * gate_w[(2*DD+d)*4+e];
        float tc = time_cond[b * DD + d];
        float s  = tc / (1.f + expf(-tc));   // silu
        #pragma unroll
        for (int j = 0; j < 8; j++) acc[4 + j] += s * time_w[d*8 + j];
    }
    #pragma unroll
    for (int k = 0; k < 12; k++) red[k][t] = acc[k];
    __syncthreads();
    for (int s = 128; s > 0; s >>= 1) {
        if (t < s) {
            #pragma unroll
            for (int k = 0; k < 12; k++) red[k][t] += red[k][t + s];
        }
        __syncthreads();
    }
    if (t == 0) {
        float logit[4], prob[4];
        #pragma unroll
        for (int e = 0; e < 4; e++) {
            float sc = red[4 + e][0] + time_b[e];
            float sh = red[8 + e][0] + time_b[4 + e];
            logit[e] = (red[e][0] + gate_b[e]) * (1.f + sc) + sh;
        }
        float mx = fmaxf(fmaxf(logit[0], logit[1]), fmaxf(logit[2], logit[3]));
        float sum = 0.f;
        for (int e = 0; e < 4; e++) { prob[e] = expf(logit[e] - mx); sum += prob[e]; }
        for (int e = 0; e < 4; e++) prob[e] /= sum;
        int i1 = 0;
        for (int e = 1; e < 4; e++) if (prob[e] > prob[i1]) i1 = e;
        int i2 = -1;
        for (int e = 0; e < 4; e++) if (e != i1 && (i2 < 0 || prob[e] > prob[i2])) i2 = e;
        float denom = prob[i1] + prob[i2] + 1e-8f;
        #pragma unroll
        for (int e = 0; e < 4; e++) g_wbe[b * NE + e] = 0.f;
        g_wbe[b * NE + i1] = prob[i1] / denom;
        g_wbe[b * NE + i2] = prob[i2] / denom;
    }
}

// ---------------- fp32 -> fp16 conversion into selected scratch buffer ----------------
__global__ void k_f2h(const float* __restrict__ src, int sel, int n4) {
    __half* dst;
    switch (sel) {
        case 0:  dst = g_Xh;  break;
        case 1:  dst = g_W1e; break;
        case 2:  dst = g_W2e; break;
        case 3:  dst = g_W1s; break;
        default: dst = g_W2s; break;
    }
    int stride = gridDim.x * blockDim.x;
    for (int i = blockIdx.x * blockDim.x + threadIdx.x; i < n4; i += stride) {
        float4 v = reinterpret_cast<const float4*>(src)[i];
        __half2* d2 = reinterpret_cast<__half2*>(dst) + (size_t)i * 2;
        d2[0] = __floats2half2_rn(v.x, v.y);
        d2[1] = __floats2half2_rn(v.z, v.w);
    }
}

// ---------------- GEMM1: H = gelu(X @ W1 + b1), fp16 out, per-tile skip ----------------
__global__ void __launch_bounds__(256, 2) k_gemm1(const float* __restrict__ bias, int expert)
{
    int bm = blockIdx.x, bn = blockIdx.y;
    if (tile_weight(expert, bm) == 0.f) return;
    const __half* A = g_Xh;
    const __half* B = (expert < 0) ? g_W1s : (g_W1e + (size_t)expert * DD * HH);
    const int K = DD, N = HH;
    int m0 = bm * BM, n0 = bn * BN;
    int tid = threadIdx.x, warp = tid >> 5, lane = tid & 31;
    int wm = warp >> 1, wn = warp & 1;

    __shared__ __align__(32) __half As[2][BM * LDA];
    __shared__ __align__(32) __half Bs[2][BK * LDB];

    wmma::fragment<wmma::accumulator, 16, 16, 16, float> acc[2][4];
    #pragma unroll
    for (int i = 0; i < 2; i++)
        #pragma unroll
        for (int j = 0; j < 4; j++) wmma::fill_fragment(acc[i][j], 0.f);

    load_tiles(As[0], Bs[0], A, B, m0, n0, 0, K, N, tid);
    cp_commit();

    const int KT = K / BK;
    for (int kt = 0; kt < KT; ++kt) {
        cp_wait0();
        __syncthreads();
        if (kt + 1 < KT) {
            load_tiles(As[(kt + 1) & 1], Bs[(kt + 1) & 1], A, B, m0, n0, (kt + 1) * BK, K, N, tid);
            cp_commit();
        }
        const __half* as = As[kt & 1];
        const __half* bs = Bs[kt & 1];
        #pragma unroll
        for (int kk = 0; kk < 2; ++kk) {
            wmma::fragment<wmma::matrix_a, 16, 16, 16, __half, wmma::row_major> af[2];
            wmma::fragment<wmma::matrix_b, 16, 16, 16, __half, wmma::row_major> bf[4];
            #pragma unroll
            for (int i = 0; i < 2; i++)
                wmma::load_matrix_sync(af[i], as + (wm * 32 + i * 16) * LDA + kk * 16, LDA);
            #pragma unroll
            for (int j = 0; j < 4; j++)
                wmma::load_matrix_sync(bf[j], bs + (kk * 16) * LDB + wn * 64 + j * 16, LDB);
            #pragma unroll
            for (int i = 0; i < 2; i++)
                #pragma unroll
                for (int j = 0; j < 4; j++)
                    wmma::mma_sync(acc[i][j], af[i], bf[j], acc[i][j]);
        }
        __syncthreads();
    }

    float* patch = reinterpret_cast<float*>(&As[0][0]) + warp * 256;
    #pragma unroll
    for (int i = 0; i < 2; i++) {
        #pragma unroll
        for (int j = 0; j < 4; j++) {
            wmma::store_matrix_sync(patch, acc[i][j], 16, wmma::mem_row_major);
            __syncwarp();
            int gm0 = m0 + wm * 32 + i * 16;
            int gn0 = n0 + wn * 64 + j * 16;
            #pragma unroll
            for (int q = lane; q < 256; q += 32) {
                int r = q >> 4, c = q & 15;
                float v = patch[q] + bias[gn0 + c];
                g_H[(size_t)(gm0 + r) * HH + gn0 + c] = __float2half(gelu_t(v));
            }
            __syncwarp();
        }
    }
}

// ---------------- GEMM2: out (=/+= w*) (H @ W2 + b2), fp32 out ----------------
__global__ void __launch_bounds__(256, 2) k_gemm2(const float* __restrict__ bias,
                                                  float* __restrict__ out,
                                                  int expert, int first)
{
    int bm = blockIdx.x, bn = blockIdx.y;
    float bw = tile_weight(expert, bm);
    if (bw == 0.f) return;
    const __half* A = g_H;
    const __half* B = (expert < 0) ? g_W2s : (g_W2e + (size_t)expert * HH * DD);
    const int K = HH, N = DD;
    int m0 = bm * BM, n0 = bn * BN;
    int tid = threadIdx.x, warp = tid >> 5, lane = tid & 31;
    int wm = warp >> 1, wn = warp & 1;

    __shared__ __align__(32) __half As[2][BM * LDA];
    __shared__ __align__(32) __half Bs[2][BK * LDB];

    wmma::fragment<wmma::accumulator, 16, 16, 16, float> acc[2][4];
    #pragma unroll
    for (int i = 0; i < 2; i++)
        #pragma unroll
        for (int j = 0; j < 4; j++) wmma::fill_fragment(acc[i][j], 0.f);

    load_tiles(As[0], Bs[0], A, B, m0, n0, 0, K, N, tid);
    cp_commit();

    const int KT = K / BK;
    for (int kt = 0; kt < KT; ++kt) {
        cp_wait0();
        __syncthreads();
        if (kt + 1 < KT) {
            load_tiles(As[(kt + 1) & 1], Bs[(kt + 1) & 1], A, B, m0, n0, (kt + 1) * BK, K, N, tid);
            cp_commit();
        }
        const __half* as = As[kt & 1];
        const __half* bs = Bs[kt & 1];
        #pragma unroll
        for (int kk = 0; kk < 2; ++kk) {
            wmma::fragment<wmma::matrix_a, 16, 16, 16, __half, wmma::row_major> af[2];
            wmma::fragment<wmma::matrix_b, 16, 16, 16, __half, wmma::row_major> bf[4];
            #pragma unroll
            for (int i = 0; i < 2; i++)
                wmma::load_matrix_sync(af[i], as + (wm * 32 + i * 16) * LDA + kk * 16, LDA);
            #pragma unroll
            for (int j = 0; j < 4; j++)
                wmma::load_matrix_sync(bf[j], bs + (kk * 16) * LDB + wn * 64 + j * 16, LDB);
            #pragma unroll
            for (int i = 0; i < 2; i++)
                #pragma unroll
                for (int j = 0; j < 4; j++)
                    wmma::mma_sync(acc[i][j], af[i], bf[j], acc[i][j]);
        }
        __syncthreads();
    }

    float* patch = reinterpret_cast<float*>(&As[0][0]) + warp * 256;
    #pragma unroll
    for (int i = 0; i < 2; i++) {
        #pragma unroll
        for (int j = 0; j < 4; j++) {
            wmma::store_matrix_sync(patch, acc[i][j], 16, wmma::mem_row_major);
            __syncwarp();
            int gm0 = m0 + wm * 32 + i * 16;
            int gn0 = n0 + wn * 64 + j * 16;
            #pragma unroll
            for (int q = lane; q < 256; q += 32) {
                int r = q >> 4, c = q & 15;
                float v = patch[q] + bias[gn0 + c];
                size_t o = (size_t)(gm0 + r) * DD + gn0 + c;
                if (first) out[o] = v;
                else       out[o] += bw * v;
            }
            __syncwarp();
        }
    }
}

// ---------------- launch ----------------
extern "C" void kernel_launch(void* const* d_in, const int* in_sizes, int n_in,
                              void* d_out, int out_size)
{
    (void)in_sizes; (void)n_in; (void)out_size;
    const float* x         = (const float*)d_in[0];
    const float* time_cond = (const float*)d_in[1];
    const float* gate_w    = (const float*)d_in[2];
    const float* gate_b    = (const float*)d_in[3];
    const float* time_w    = (const float*)d_in[4];
    const float* time_b    = (const float*)d_in[5];
    const float* ew1       = (const float*)d_in[6];
    const float* eb1       = (const float*)d_in[7];
    const float* ew2       = (const float*)d_in[8];
    const float* eb2       = (const float*)d_in[9];
    const float* sw1       = (const float*)d_in[10];
    const float* sb1       = (const float*)d_in[11];
    const float* sw2       = (const float*)d_in[12];
    const float* sb2       = (const float*)d_in[13];
    float* out = (float*)d_out;

    // gating
    k_stageA<<<dim3(8, 6), 256>>>(x);
    k_gate<<<8, 256>>>(gate_w, gate_b, time_cond, time_w, time_b);

    // fp32 -> fp16 conversions
    k_f2h<<<2048, 256>>>(x,   0, MT * DD / 4);
    k_f2h<<<4096, 256>>>(ew1, 1, NE * DD * HH / 4);
    k_f2h<<<4096, 256>>>(ew2, 2, NE * HH * DD / 4);
    k_f2h<<<2048, 256>>>(sw1, 3, DD * HH / 4);
    k_f2h<<<2048, 256>>>(sw2, 4, HH * DD / 4);

    // shared expert first (writes every output element with '=')
    k_gemm1<<<dim3(MT / BM, HH / BN), 256>>>(sb1, -1);
    k_gemm2<<<dim3(MT / BM, DD / BN), 256>>>(sb2, out, -1, 1);

    // routed experts (tiles with zero weight exit immediately)
    for (int e = 0; e < NE; ++e) {
        k_gemm1<<<dim3(MT / BM, HH / BN), 256>>>(eb1 + (size_t)e * HH, e);
        k_gemm2<<<dim3(MT / BM, DD / BN), 256>>>(eb2 + (size_t)e * DD, out, e, 0);
    }
}

// round 3
// speedup vs baseline: 1.6375x; 1.6375x over previous
#include <cuda_runtime.h>
#include <cuda_fp16.h>
#include <cstdint>

#define DD 1024
#define HH 4096
#define NB 8
#define LL 768
#define MT 6144   // NB*LL
#define NE 4

#define KCH 64               // K halfs per chunk (128B rows)
#define SS 3                 // pipeline stages
#define TILE_BYTES 16384     // 128 rows x 128B
#define STG_BYTES 32768      // A tile + B tile
#define GEMM_SMEM (SS * STG_BYTES)

// ---------------- scratch (device globals; no allocation) ----------------
__device__ __align__(256) __half g_Xh[(size_t)MT * DD];
__device__ __align__(256) __half g_W1e[(size_t)NE * HH * DD];  // W1^T per expert: [H][D]
__device__ __align__(256) __half g_W2e[(size_t)NE * DD * HH];  // W2^T per expert: [D][H]
__device__ __align__(256) __half g_W1s[(size_t)HH * DD];       // sw1^T
__device__ __align__(256) __half g_W2s[(size_t)DD * HH];       // sw2^T
__device__ __align__(256) __half g_H[(size_t)5 * MT * HH];     // [shared, e0..e3] hidden
__device__ float  g_partial[NB * 6 * DD];
__device__ float  g_wbe[NB * NE];

// ---------------- helpers ----------------
__device__ __forceinline__ uint32_t smem_u32(const void* p) {
    uint32_t a;
    asm("{ .reg .u64 t; cvta.to.shared.u64 t, %1; cvt.u32.u64 %0, t; }" : "=r"(a) : "l"(p));
    return a;
}
__device__ __forceinline__ void cp_async16(void* smem, const void* gmem) {
    unsigned s = (unsigned)__cvta_generic_to_shared(smem);
    asm volatile("cp.async.cg.shared.global [%0], [%1], 16;\n" :: "r"(s), "l"(gmem) : "memory");
}
__device__ __forceinline__ void cp_commit() { asm volatile("cp.async.commit_group;\n" ::: "memory"); }

__device__ __forceinline__ void ldm4(uint32_t* r, uint32_t addr) {
    asm volatile("ldmatrix.sync.aligned.m8n8.x4.shared.b16 {%0,%1,%2,%3}, [%4];"
        : "=r"(r[0]), "=r"(r[1]), "=r"(r[2]), "=r"(r[3]) : "r"(addr));
}
__device__ __forceinline__ void mma16816(float* c, const uint32_t* a, const uint32_t* b) {
    asm volatile(
        "mma.sync.aligned.m16n8k16.row.col.f32.f16.f16.f32 "
        "{%0,%1,%2,%3}, {%4,%5,%6,%7}, {%8,%9}, {%0,%1,%2,%3};"
        : "+f"(c[0]), "+f"(c[1]), "+f"(c[2]), "+f"(c[3])
        : "r"(a[0]), "r"(a[1]), "r"(a[2]), "r"(a[3]), "r"(b[0]), "r"(b[1]));
}

__device__ __forceinline__ float gelu_t(float v) {
    float c = v + 0.044715f * v * v * v;
    return 0.5f * v * (1.f + tanhf(0.7978845608028654f * c));
}

// per-M-tile weight: batch gating weight x third-mask; exact 0 => skip tile
__device__ __forceinline__ float tile_weight(int expert, int bm) {
    if (expert < 0) return 1.f;
    int b = bm / 6;             // 6 tiles of 128 tokens per batch
    int third = (bm % 6) >> 1;  // 0 head, 1 wrist, 2 proprio
    if (expert == 1 && third == 1) return 0.f;
    if (expert == 2 && third == 0) return 0.f;
    return g_wbe[b * NE + expert];
}

// ---------------- gating stage A ----------------
__global__ void k_stageA(const float* __restrict__ x) {
    int b = blockIdx.x, c = blockIdx.y, t = threadIdx.x;
    const float* base = x + ((size_t)(b * LL + c * 128)) * DD;
    for (int d = t; d < DD; d += 256) {
        float s = 0.f;
        #pragma unroll 4
        for (int l = 0; l < 128; ++l) s += base[(size_t)l * DD + d];
        g_partial[(b * 6 + c) * DD + d] = s;
    }
}

// ---------------- gating stage B ----------------
__global__ void k_gate(const float* __restrict__ gate_w, const float* __restrict__ gate_b,
                       const float* __restrict__ time_cond, const float* __restrict__ time_w,
                       const float* __restrict__ time_b)
{
    int b = blockIdx.x, t = threadIdx.x;
    __shared__ float red[12][256];
    float acc[12];
    #pragma unroll
    for (int k = 0; k < 12; k++) acc[k] = 0.f;
    for (int d = t; d < DD; d += 256) {
        float h = g_partial[(b*6+0)*DD+d] + g_partial[(b*6+1)*DD+d];
        float w = g_partial[(b*6+2)*DD+d] + g_partial[(b*6+3)*DD+d];
        float p = g_partial[(b*6+4)*DD+d] + g_partial[(b*6+5)*DD+d];
        float full = (h + w + p) * (1.f / 768.f);
        float hp   = (h + p) * (1.f / 512.f);
        float wp   = (w + p) * (1.f / 512.f);
        #pragma unroll
        for (int e = 0; e < 4; e++)
            acc[e] += full * gate_w[d*4+e] + hp * gate_w[(DD+d)*4+e] + wp * gate_w[(2*DD+d)*4+e];
        float tc = time_cond[b * DD + d];
        float s  = tc / (1.f + expf(-tc));   // silu
        #pragma unroll
        for (int j = 0; j < 8; j++) acc[4 + j] += s * time_w[d*8 + j];
    }
    #pragma unroll
    for (int k = 0; k < 12; k++) red[k][t] = acc[k];
    __syncthreads();
    for (int s = 128; s > 0; s >>= 1) {
        if (t < s) {
            #pragma unroll
            for (int k = 0; k < 12; k++) red[k][t] += red[k][t + s];
        }
        __syncthreads();
    }
    if (t == 0) {
        float logit[4], prob[4];
        #pragma unroll
        for (int e = 0; e < 4; e++) {
            float sc = red[4 + e][0] + time_b[e];
            float sh = red[8 + e][0] + time_b[4 + e];
            logit[e] = (red[e][0] + gate_b[e]) * (1.f + sc) + sh;
        }
        float mx = fmaxf(fmaxf(logit[0], logit[1]), fmaxf(logit[2], logit[3]));
        float sum = 0.f;
        for (int e = 0; e < 4; e++) { prob[e] = expf(logit[e] - mx); sum += prob[e]; }
        for (int e = 0; e < 4; e++) prob[e] /= sum;
        int i1 = 0;
        for (int e = 1; e < 4; e++) if (prob[e] > prob[i1]) i1 = e;
        int i2 = -1;
        for (int e = 0; e < 4; e++) if (e != i1 && (i2 < 0 || prob[e] > prob[i2])) i2 = e;
        float denom = prob[i1] + prob[i2] + 1e-8f;
        #pragma unroll
        for (int e = 0; e < 4; e++) g_wbe[b * NE + e] = 0.f;
        g_wbe[b * NE + i1] = prob[i1] / denom;
        g_wbe[b * NE + i2] = prob[i2] / denom;
    }
}

// ---------------- fp32 -> fp16 straight convert (x -> g_Xh) ----------------
__global__ void k_f2h(const float* __restrict__ src, int n4) {
    int stride = gridDim.x * blockDim.x;
    for (int i = blockIdx.x * blockDim.x + threadIdx.x; i < n4; i += stride) {
        float4 v = reinterpret_cast<const float4*>(src)[i];
        __half2* d2 = reinterpret_cast<__half2*>(g_Xh) + (size_t)i * 2;
        d2[0] = __floats2half2_rn(v.x, v.y);
        d2[1] = __floats2half2_rn(v.z, v.w);
    }
}

// ---------------- fp32 [R,C] -> fp16 transposed [C,R] into selected buffer ----------------
__global__ void k_f2ht(const float* __restrict__ src, int sel, int R, int C) {
    __half* dst;
    switch (sel) {
        case 0:  dst = g_W1e; break;
        case 1:  dst = g_W2e; break;
        case 2:  dst = g_W1s; break;
        default: dst = g_W2s; break;
    }
    int e = blockIdx.z;
    src += (size_t)e * R * C;
    dst += (size_t)e * R * C;
    __shared__ float t[32][33];
    int c0 = blockIdx.x * 32, r0 = blockIdx.y * 32;
    int tx = threadIdx.x, ty = threadIdx.y;
    #pragma unroll
    for (int j = 0; j < 32; j += 8)
        t[ty + j][tx] = src[(size_t)(r0 + ty + j) * C + c0 + tx];
    __syncthreads();
    #pragma unroll
    for (int j = 0; j < 32; j += 8)
        dst[(size_t)(c0 + ty + j) * R + r0 + tx] = __float2half(t[tx][ty + j]);
}

// ---------------- fused mma.sync GEMM ----------------
// mode 0 (GEMM1): z selects buffer (0 shared, 1..4 experts). H[z] = w * gelu(X@W1 + b1)
// mode 1 (GEMM2): out = sum over active segs s:  H[s] @ W2[s]  + combined bias (one write)
__global__ void __launch_bounds__(256, 2) k_mma(
    const float* __restrict__ b_sh, const float* __restrict__ b_ex,
    float* __restrict__ fout, int mode)
{
    int bm = blockIdx.x, bn = blockIdx.y, z = blockIdx.z;
    __shared__ const __half* sA[5];
    __shared__ const __half* sB[5];
    __shared__ const float* sBias[5];
    __shared__ float sW[5];
    __shared__ int sNs;

    int Ks, nch;
    float scale = 1.f;
    __half* hout = nullptr;

    if (mode == 0) {
        float w = tile_weight(z - 1, bm);
        if (w == 0.f) return;
        scale = w;
        if (threadIdx.x == 0) {
            sA[0] = g_Xh;
            sB[0] = (z == 0) ? g_W1s : (g_W1e + (size_t)(z - 1) * HH * DD);
            sBias[0] = (z == 0) ? b_sh : (b_ex + (size_t)(z - 1) * HH);
            sNs = 1;
        }
        Ks = DD;
        hout = g_H + (size_t)z * MT * HH;
    } else {
        if (threadIdx.x == 0) {
            int ns = 0;
            sA[ns] = g_H; sB[ns] = g_W2s; sBias[ns] = b_sh; sW[ns] = 1.f; ns++;
            for (int e = 0; e < NE; e++) {
                float w = tile_weight(e, bm);
                if (w > 0.f) {
                    sA[ns] = g_H + (size_t)(e + 1) * MT * HH;
                    sB[ns] = g_W2e + (size_t)e * DD * HH;
                    sBias[ns] = b_ex + (size_t)e * DD;
                    sW[ns] = w;
                    ns++;
                }
            }
            sNs = ns;
        }
        Ks = HH;
    }
    __syncthreads();
    int ns = sNs;
    nch = (mode == 0) ? (DD / KCH) : ns * (HH / KCH);

    extern __shared__ __align__(128) char smem[];
    uint32_t sbase = smem_u32(smem);
    int tid = threadIdx.x, lane = tid & 31, wid = tid >> 5;
    int wm = wid & 3, wn = wid >> 2;
    int m0 = bm * 128, n0 = bn * 128;

    auto issue = [&](int flat, int slot) {
        int seg = flat >> 6;
        int koff = (flat & 63) * KCH;
        const __half* Ab = sA[seg] + koff;
        const __half* Bb = sB[seg] + koff;
        char* st = smem + slot * STG_BYTES;
        #pragma unroll
        for (int i = 0; i < 4; i++) {
            int idx = tid + i * 256;
            int r = idx >> 3, c8 = idx & 7;
            uint32_t off = (uint32_t)(r * 128 + c8 * 16);
            off ^= (off >> 3) & 0x70;
            cp_async16(st + off, Ab + (size_t)(m0 + r) * Ks + c8 * 8);
        }
        #pragma unroll
        for (int i = 0; i < 4; i++) {
            int idx = tid + i * 256;
            int r = idx >> 3, c8 = idx & 7;
            uint32_t off = (uint32_t)(r * 128 + c8 * 16);
            off ^= (off >> 3) & 0x70;
            cp_async16(st + TILE_BYTES + off, Bb + (size_t)(n0 + r) * Ks + c8 * 8);
        }
        cp_commit();
    };

    float c[2][8][4];
    #pragma unroll
    for (int i = 0; i < 2; i++)
        #pragma unroll
        for (int j = 0; j < 8; j++)
            #pragma unroll
            for (int q = 0; q < 4; q++) c[i][j][q] = 0.f;

    issue(0, 0);
    issue(1, 1);

    for (int it = 0; it < nch; ++it) {
        if (it + 1 < nch) asm volatile("cp.async.wait_group 1;" ::: "memory");
        else              asm volatile("cp.async.wait_group 0;" ::: "memory");
        __syncthreads();
        if (it + 2 < nch) issue(it + 2, (it + 2) % SS);

        uint32_t sAb = sbase + (it % SS) * STG_BYTES;
        uint32_t sBb = sAb + TILE_BYTES;
        #pragma unroll
        for (int kk = 0; kk < 4; kk++) {
            uint32_t a[2][4];
            #pragma unroll
            for (int i = 0; i < 2; i++) {
                int row = wm * 32 + i * 16 + (lane & 15);
                uint32_t off = (uint32_t)(row * 128 + kk * 32 + ((lane >> 4) & 1) * 16);
                off ^= (off >> 3) & 0x70;
                ldm4(a[i], sAb + off);
            }
            uint32_t b[8][2];
            #pragma unroll
            for (int jp = 0; jp < 4; jp++) {
                int n = wn * 64 + jp * 16 + ((lane >> 4) & 1) * 8 + (lane & 7);
                uint32_t off = (uint32_t)(n * 128 + kk * 32 + ((lane >> 3) & 1) * 16);
                off ^= (off >> 3) & 0x70;
                uint32_t r4[4];
                ldm4(r4, sBb + off);
                b[2 * jp][0] = r4[0]; b[2 * jp][1] = r4[1];
                b[2 * jp + 1][0] = r4[2]; b[2 * jp + 1][1] = r4[3];
            }
            #pragma unroll
            for (int i = 0; i < 2; i++)
                #pragma unroll
                for (int j = 0; j < 8; j++)
                    mma16816(c[i][j], a[i], b[j]);
        }
    }

    // ---- epilogue (register-direct) ----
    int gid = lane >> 2, tig = lane & 3;
    if (mode == 0) {
        #pragma unroll
        for (int i = 0; i < 2; i++) {
            int r0i = m0 + wm * 32 + i * 16 + gid;
            #pragma unroll
            for (int j = 0; j < 8; j++) {
                int col = n0 + wn * 64 + j * 8 + tig * 2;
                float b0 = __ldg(sBias[0] + col);
                float b1 = __ldg(sBias[0] + col + 1);
                __half2 h0 = __floats2half2_rn(scale * gelu_t(c[i][j][0] + b0),
                                               scale * gelu_t(c[i][j][1] + b1));
                __half2 h1 = __floats2half2_rn(scale * gelu_t(c[i][j][2] + b0),
                                               scale * gelu_t(c[i][j][3] + b1));
                *reinterpret_cast<__half2*>(hout + (size_t)r0i * HH + col) = h0;
                *reinterpret_cast<__half2*>(hout + (size_t)(r0i + 8) * HH + col) = h1;
            }
        }
    } else {
        #pragma unroll
        for (int i = 0; i < 2; i++) {
            int r0i = m0 + wm * 32 + i * 16 + gid;
            #pragma unroll
            for (int j = 0; j < 8; j++) {
                int col = n0 + wn * 64 + j * 8 + tig * 2;
                float b0 = __ldg(sBias[0] + col);
                float b1 = __ldg(sBias[0] + col + 1);
                for (int s = 1; s < ns; s++) {
                    b0 += sW[s] * __ldg(sBias[s] + col);
                    b1 += sW[s] * __ldg(sBias[s] + col + 1);
                }
                float2 v0 = make_float2(c[i][j][0] + b0, c[i][j][1] + b1);
                float2 v1 = make_float2(c[i][j][2] + b0, c[i][j][3] + b1);
                *reinterpret_cast<float2*>(fout + (size_t)r0i * DD + col) = v0;
                *reinterpret_cast<float2*>(fout + (size_t)(r0i + 8) * DD + col) = v1;
            }
        }
    }
}

// ---------------- launch ----------------
extern "C" void kernel_launch(void* const* d_in, const int* in_sizes, int n_in,
                              void* d_out, int out_size)
{
    (void)in_sizes; (void)n_in; (void)out_size;
    const float* x         = (const float*)d_in[0];
    const float* time_cond = (const float*)d_in[1];
    const float* gate_w    = (const float*)d_in[2];
    const float* gate_b    = (const float*)d_in[3];
    const float* time_w    = (const float*)d_in[4];
    const float* time_b    = (const float*)d_in[5];
    const float* ew1       = (const float*)d_in[6];
    const float* eb1       = (const float*)d_in[7];
    const float* ew2       = (const float*)d_in[8];
    const float* eb2       = (const float*)d_in[9];
    const float* sw1       = (const float*)d_in[10];
    const float* sb1       = (const float*)d_in[11];
    const float* sw2       = (const float*)d_in[12];
    const float* sb2       = (const float*)d_in[13];
    float* out = (float*)d_out;

    cudaFuncSetAttribute(k_mma, cudaFuncAttributeMaxDynamicSharedMemorySize, GEMM_SMEM);

    // gating
    k_stageA<<<dim3(8, 6), 256>>>(x);
    k_gate<<<8, 256>>>(gate_w, gate_b, time_cond, time_w, time_b);

    // conversions: x straight; weights transposed to [N][K] fp16
    k_f2h<<<2048, 256>>>(x, MT * DD / 4);
    k_f2ht<<<dim3(HH / 32, DD / 32, NE), dim3(32, 8)>>>(ew1, 0, DD, HH); // [D,H]->[H,D]
    k_f2ht<<<dim3(DD / 32, HH / 32, NE), dim3(32, 8)>>>(ew2, 1, HH, DD); // [H,D]->[D,H]
    k_f2ht<<<dim3(HH / 32, DD / 32, 1),  dim3(32, 8)>>>(sw1, 2, DD, HH);
    k_f2ht<<<dim3(DD / 32, HH / 32, 1),  dim3(32, 8)>>>(sw2, 3, HH, DD);

    // GEMM1: shared + 4 experts in one launch (z dim); inactive tiles exit
    k_mma<<<dim3(MT / 128, HH / 128, 5), 256, GEMM_SMEM>>>(sb1, eb1, nullptr, 0);
    // GEMM2: fused accumulation over active segments, single write of out
    k_mma<<<dim3(MT / 128, DD / 128, 1), 256, GEMM_SMEM>>>(sb2, eb2, out, 1);
}